// round 11
// baseline (speedup 1.0000x reference)
#include <cuda_runtime.h>
#include <cuda_fp16.h>
#include <cstdint>
#include <cstddef>

#define BB 32
#define TT 4096
#define DD 512
#define HH 512

// Scratch (device globals; no allocation allowed)
__device__ float g_WW[DD * HH];        // W@Wa (fp32)
__device__ float g_cb[HH];             // bias@Wa + ba
__device__ float g_c[BB * HH];         // hid@WW + cb
__device__ __half g_BhT[HH * DD];      // fp16 (U@Wa)^T  [h][k]
__device__ float g_cij[BB * TT];
__device__ float g_pout[1024 * DD];    // per-chunk partial weighted sums
__device__ float g_ms[1024];           // per-chunk local max
__device__ float g_ss[1024];           // per-chunk local sum-exp

// ---------------------------------------------------------------------------
// PTX helpers (family-portable: mma.sync + cp.async + ldmatrix)
// ---------------------------------------------------------------------------
__device__ __forceinline__ uint32_t smem_u32(const void* p) {
    uint32_t a;
    asm("{ .reg .u64 t; cvta.to.shared.u64 t, %1; cvt.u32.u64 %0, t; }" : "=r"(a) : "l"(p));
    return a;
}
__device__ __forceinline__ void cpa16(uint32_t dst, const void* src) {
    asm volatile("cp.async.cg.shared.global [%0], [%1], 16;" :: "r"(dst), "l"(src));
}
#define CPA_COMMIT() asm volatile("cp.async.commit_group;" ::: "memory")
#define CPA_WAIT0()  asm volatile("cp.async.wait_group 0;" ::: "memory")

__device__ __forceinline__ float tanh_fast(float x) {
    float y;
    asm("tanh.approx.f32 %0, %1;" : "=f"(y) : "f"(x));
    return y;
}

__device__ __forceinline__ void ldm_x4(uint32_t* r, uint32_t addr) {
    asm volatile("ldmatrix.sync.aligned.m8n8.x4.shared.b16 {%0,%1,%2,%3}, [%4];"
                 : "=r"(r[0]), "=r"(r[1]), "=r"(r[2]), "=r"(r[3]) : "r"(addr));
}

__device__ __forceinline__ void mma16816h_full(float* d, const uint32_t* a, const uint32_t* b) {
    asm volatile(
        "mma.sync.aligned.m16n8k16.row.col.f32.f16.f16.f32 "
        "{%0,%1,%2,%3}, {%4,%5,%6,%7}, {%8,%9}, {%0,%1,%2,%3};"
        : "+f"(d[0]), "+f"(d[1]), "+f"(d[2]), "+f"(d[3])
        : "r"(a[0]), "r"(a[1]), "r"(a[2]), "r"(a[3]), "r"(b[0]), "r"(b[1]));
}
#define MMA16816H mma16816h_full

// ---------------------------------------------------------------------------
// biggemm: Y = X @ Wa, tiled 64x64x16, 256 threads, 4x4 micro-tile.
//   mode 0: X = [W; bias] (513 rows) -> WW fp32 rows<512, cb = row512 + ba
//   mode 1: X = U (512 rows)         -> BhT[col][row] = fp16(Y[row][col])
// ---------------------------------------------------------------------------
__global__ void __launch_bounds__(256)
biggemm(const float* __restrict__ X, const float* __restrict__ bias,
        const float* __restrict__ Wa, const float* __restrict__ ba,
        float* __restrict__ WW, float* __restrict__ cb,
        __half* __restrict__ BhT, int mode)
{
    __shared__ float As[16][68];
    __shared__ float Bs[16][64];
    const int tid = threadIdx.x;
    const int r0 = blockIdx.x * 64, c0 = blockIdx.y * 64;
    const int tx = tid & 15, ty = tid >> 4;

    float acc[4][4];
#pragma unroll
    for (int i = 0; i < 4; i++)
#pragma unroll
        for (int j = 0; j < 4; j++) acc[i][j] = 0.0f;

    for (int k0 = 0; k0 < 512; k0 += 16) {
        {
            int row = tid >> 2, seg = tid & 3;
            int gr = r0 + row;
            float4 v = make_float4(0.f, 0.f, 0.f, 0.f);
            if (gr < 512)                    v = *(const float4*)(X + (size_t)gr * 512 + k0 + seg * 4);
            else if (gr == 512 && mode == 0) v = *(const float4*)(bias + k0 + seg * 4);
            As[seg * 4 + 0][row] = v.x;
            As[seg * 4 + 1][row] = v.y;
            As[seg * 4 + 2][row] = v.z;
            As[seg * 4 + 3][row] = v.w;
        }
        {
            int kk = tid >> 4, seg = tid & 15;
            *(float4*)&Bs[kk][seg * 4] =
                *(const float4*)(Wa + (size_t)(k0 + kk) * 512 + c0 + seg * 4);
        }
        __syncthreads();

#pragma unroll
        for (int kk = 0; kk < 16; kk++) {
            float4 a4 = *(float4*)&As[kk][ty * 4];
            float4 b4 = *(float4*)&Bs[kk][tx * 4];
            float av[4] = {a4.x, a4.y, a4.z, a4.w};
            float bv[4] = {b4.x, b4.y, b4.z, b4.w};
#pragma unroll
            for (int i = 0; i < 4; i++)
#pragma unroll
                for (int j = 0; j < 4; j++) acc[i][j] += av[i] * bv[j];
        }
        __syncthreads();
    }

    if (mode == 0) {
#pragma unroll
        for (int i = 0; i < 4; i++) {
            int r = r0 + ty * 4 + i;
            if (r < 512) {
#pragma unroll
                for (int j = 0; j < 4; j++)
                    WW[(size_t)r * 512 + c0 + tx * 4 + j] = acc[i][j];
            } else if (r == 512) {
#pragma unroll
                for (int j = 0; j < 4; j++)
                    cb[c0 + tx * 4 + j] = acc[i][j] + ba[c0 + tx * 4 + j];
            }
        }
    } else {
#pragma unroll
        for (int j = 0; j < 4; j++) {
            int col = c0 + tx * 4 + j;
            __half2 p0 = __floats2half2_rn(acc[0][j], acc[1][j]);
            __half2 p1 = __floats2half2_rn(acc[2][j], acc[3][j]);
            *(uint2*)(BhT + (size_t)col * 512 + r0 + ty * 4) =
                make_uint2(*(uint32_t*)&p0, *(uint32_t*)&p1);
        }
    }
}

// ---------------------------------------------------------------------------
// cgemm: c[b][j] = sum_d hid[b][d] * WW[d][j] + cb[j]   (32 x 512, K=512)
// ---------------------------------------------------------------------------
__global__ void __launch_bounds__(256)
cgemm(const float* __restrict__ hid, const float* __restrict__ WW,
      const float* __restrict__ cb, float* __restrict__ c)
{
    __shared__ float hs[32][132];
    const int tid = threadIdx.x;
    const int col = blockIdx.x * 32 + (tid & 31);
    const int rg = tid >> 5;

    float acc[4] = {0.f, 0.f, 0.f, 0.f};
    for (int d0 = 0; d0 < 512; d0 += 128) {
        for (int v = tid; v < 1024; v += 256) {
            int row = v >> 5, seg = v & 31;
            *(float4*)&hs[row][seg * 4] =
                *(const float4*)(hid + (size_t)row * 512 + d0 + seg * 4);
        }
        __syncthreads();
#pragma unroll 8
        for (int dd = 0; dd < 128; dd++) {
            float bv = WW[(size_t)(d0 + dd) * 512 + col];
#pragma unroll
            for (int i = 0; i < 4; i++) acc[i] += hs[rg * 4 + i][dd] * bv;
        }
        __syncthreads();
    }
#pragma unroll
    for (int i = 0; i < 4; i++)
        c[(size_t)(rg * 4 + i) * 512 + col] = acc[i] + cb[col];
}

// ---------------------------------------------------------------------------
// Main mma.sync kernel + fused flash-style partial softmax/weighted-sum.
// A fragments loaded DIRECTLY from global fp32 (LDG.64 -> cvt -> regs);
// no A smem staging. B via cp.async double-buffer + ldmatrix.
// ---------------------------------------------------------------------------
#define TILE_B  10240            /* 128 rows x 80B */
#define OFF_B   0                /* + buf*TILE_B, end 20480 */
#define OFF_CS  20480
#define OFF_VS  22528
#define OFF_EP  24576            /* 256 floats */
#define OFF_CIJ 25600            /* 128 floats */
#define OFF_RED 26112            /* 16 floats */
#define SMEM_BYTES 26176

__device__ __forceinline__ void load_B_chunk(
    uint32_t sb, int buf, const __half* Bt, int h0, int k0, int tid)
{
#pragma unroll
    for (int j = 0; j < 2; j++) {
        int u = tid + j * 256;
        int row = u >> 2, seg = u & 3;
        const __half* src = Bt + (size_t)(h0 + row) * 512 + k0 + seg * 8;
        uint32_t dst = sb + OFF_B + (uint32_t)(buf * TILE_B + row * 80 + seg * 16);
        cpa16(dst, src);
    }
}

__global__ void __launch_bounds__(256, 2)
attn_mma(const float* __restrict__ E, const __half* __restrict__ Bt,
         const float* __restrict__ c, const float* __restrict__ V,
         float* __restrict__ cij,
         float* __restrict__ pout, float* __restrict__ ms, float* __restrict__ ss)
{
    extern __shared__ char sm[];
    const uint32_t sb = smem_u32(sm);
    const int tid = threadIdx.x, wid = tid >> 5, lane = tid & 31;
    const int warp_m = wid & 3;
    const int warp_n = wid >> 2;
    const int lq = lane >> 2, lr = lane & 3;
    const int row0 = blockIdx.x * 128;
    const int b = row0 >> 12;

    const float* Eb = E + (size_t)row0 * 512;
    // per-thread A base: row = warp_m*32 + lq, col = lr*2
    const float* EaT = Eb + (size_t)(warp_m * 32 + lq) * 512 + lr * 2;

    float* c_s   = (float*)(sm + OFF_CS);
    float* V_s   = (float*)(sm + OFF_VS);
    float* ep_s  = (float*)(sm + OFF_EP);
    float* cij_s = (float*)(sm + OFF_CIJ);
    float* red_s = (float*)(sm + OFF_RED);

    for (int i = tid; i < 512; i += 256) {
        c_s[i] = c[(size_t)b * 512 + i];
        V_s[i] = V[i];
    }
    if (tid < 128) cij_s[tid] = 0.0f;
    __syncthreads();

    const int arr = lane & 7;
    const int bpr = lane >> 3;

    for (int hp = 0; hp < 4; hp++) {
        const int h0 = hp * 128;
        float acc[2][8][4];
#pragma unroll
        for (int fm = 0; fm < 2; fm++)
#pragma unroll
            for (int fn = 0; fn < 8; fn++)
#pragma unroll
                for (int j = 0; j < 4; j++) acc[fm][fn][j] = 0.0f;

        load_B_chunk(sb, 0, Bt, h0, 0, tid);
        CPA_COMMIT();

        for (int kc = 0; kc < 16; kc++) {
            const int buf = kc & 1;
            CPA_WAIT0();
            __syncthreads();                 // B(kc) visible; all warps past B(kc-1)

            if (kc < 15) {
                load_B_chunk(sb, buf ^ 1, Bt, h0, (kc + 1) * 32, tid);
                CPA_COMMIT();
            }

            const uint32_t bbase = sb + OFF_B + (uint32_t)(buf * TILE_B);
            const float* pK = EaT + kc * 32;

#pragma unroll
            for (int ks = 0; ks < 2; ks++) {
                // A fragments: direct LDG.64 from global (L2-warm) -> fp16 regs
                uint32_t aF[2][4];
#pragma unroll
                for (int fm = 0; fm < 2; fm++) {
                    const float* q = pK + ks * 16 + fm * 8192;   // fm*16 rows
                    float2 v0 = *(const float2*)(q);             // row lq,   k+2lr
                    float2 v1 = *(const float2*)(q + 4096);      // row lq+8, k+2lr
                    float2 v2 = *(const float2*)(q + 8);         // row lq,   k+2lr+8
                    float2 v3 = *(const float2*)(q + 4104);      // row lq+8, k+2lr+8
                    __half2 h0 = __float22half2_rn(v0);
                    __half2 h1 = __float22half2_rn(v1);
                    __half2 h2 = __float22half2_rn(v2);
                    __half2 h3 = __float22half2_rn(v3);
                    aF[fm][0] = *(uint32_t*)&h0;
                    aF[fm][1] = *(uint32_t*)&h1;
                    aF[fm][2] = *(uint32_t*)&h2;
                    aF[fm][3] = *(uint32_t*)&h3;
                }
#pragma unroll
                for (int fnp = 0; fnp < 4; fnp++) {
                    int nrow = warp_n * 64 + fnp * 16 + (bpr >> 1) * 8 + arr;
                    uint32_t bF[4];
                    ldm_x4(bF, bbase + (uint32_t)(nrow * 80 + ks * 32 + (bpr & 1) * 16));
#pragma unroll
                    for (int fm = 0; fm < 2; fm++) {
                        MMA16816H(acc[fm][fnp * 2],     aF[fm], bF);
                        MMA16816H(acc[fm][fnp * 2 + 1], aF[fm], bF + 2);
                    }
                }
            }
        }

        // ---- epilogue for this h-pass (MUFU.TANH) ----
        float rsum[4] = {0.f, 0.f, 0.f, 0.f};
#pragma unroll
        for (int fm = 0; fm < 2; fm++)
#pragma unroll
            for (int fn = 0; fn < 8; fn++) {
                int h = h0 + warp_n * 64 + fn * 8 + lr * 2;
                float v0 = tanh_fast(acc[fm][fn][0] + c_s[h])     * V_s[h];
                float v1 = tanh_fast(acc[fm][fn][1] + c_s[h + 1]) * V_s[h + 1];
                float v2 = tanh_fast(acc[fm][fn][2] + c_s[h])     * V_s[h];
                float v3 = tanh_fast(acc[fm][fn][3] + c_s[h + 1]) * V_s[h + 1];
                rsum[fm * 2]     += v0 + v1;
                rsum[fm * 2 + 1] += v2 + v3;
            }
#pragma unroll
        for (int j = 0; j < 4; j++) {
            rsum[j] += __shfl_xor_sync(0xffffffffu, rsum[j], 1);
            rsum[j] += __shfl_xor_sync(0xffffffffu, rsum[j], 2);
        }
        if (lr == 0) {
#pragma unroll
            for (int fm = 0; fm < 2; fm++) {
                int r = warp_m * 32 + fm * 16 + lq;
                ep_s[warp_n * 128 + r]     = rsum[fm * 2];
                ep_s[warp_n * 128 + r + 8] = rsum[fm * 2 + 1];
            }
        }
        __syncthreads();
        if (tid < 128) cij_s[tid] += ep_s[tid] + ep_s[128 + tid];
        __syncthreads();
    }

    if (tid < 128) cij[row0 + tid] = cij_s[tid];
    __syncthreads();

    // ---- fused flash-style partial softmax + weighted sum ----
    float v = (tid < 128) ? cij_s[tid] : -1e30f;
#pragma unroll
    for (int off = 16; off; off >>= 1) v = fmaxf(v, __shfl_xor_sync(0xffffffffu, v, off));
    if (lane == 0) red_s[wid] = v;
    __syncthreads();
    const float mhat = fmaxf(fmaxf(red_s[0], red_s[1]), fmaxf(red_s[2], red_s[3]));

    float p = 0.0f;
    if (tid < 128) { p = __expf(cij_s[tid] - mhat); ep_s[tid] = p; }
    float sv = p;
#pragma unroll
    for (int off = 16; off; off >>= 1) sv += __shfl_xor_sync(0xffffffffu, sv, off);
    if (lane == 0) red_s[8 + wid] = sv;
    __syncthreads();
    const float S = red_s[8] + red_s[9] + red_s[10] + red_s[11];
    if (tid == 0) { ms[blockIdx.x] = mhat; ss[blockIdx.x] = S; }

    float a0 = 0.0f, a1 = 0.0f;
    for (int i = 0; i < 128; i += 8) {
#pragma unroll
        for (int j = 0; j < 8; j++) {
            float pij = ep_s[i + j];
            a0 = fmaf(pij, Eb[(size_t)(i + j) * 512 + tid],       a0);
            a1 = fmaf(pij, Eb[(size_t)(i + j) * 512 + tid + 256], a1);
        }
    }
    pout[(size_t)blockIdx.x * 512 + tid]       = a0;
    pout[(size_t)blockIdx.x * 512 + tid + 256] = a1;
}

// ---------------------------------------------------------------------------
// Finalize: combine 32 chunk-partials per batch (flash rescale) + write alphas.
// ---------------------------------------------------------------------------
__global__ void __launch_bounds__(256)
finalize(const float* __restrict__ cij, const float* __restrict__ pout,
         const float* __restrict__ ms, const float* __restrict__ ss,
         float* __restrict__ out_o, float* __restrict__ out_a)
{
    __shared__ float w_s[32];
    __shared__ float MZ[2];
    const int b = blockIdx.x, tid = threadIdx.x;

    if (tid < 32) {
        float m = ms[b * 32 + tid];
        float M = m;
#pragma unroll
        for (int off = 16; off; off >>= 1) M = fmaxf(M, __shfl_xor_sync(0xffffffffu, M, off));
        float w = __expf(m - M);
        w_s[tid] = w;
        float z = w * ss[b * 32 + tid];
#pragma unroll
        for (int off = 16; off; off >>= 1) z += __shfl_xor_sync(0xffffffffu, z, off);
        if (tid == 0) { MZ[0] = M; MZ[1] = z; }
    }
    __syncthreads();
    const float M = MZ[0], invZ = 1.0f / MZ[1];

    for (int d = tid; d < 512; d += 256) {
        float s = 0.0f;
#pragma unroll
        for (int i = 0; i < 32; i++)
            s += w_s[i] * pout[(size_t)(b * 32 + i) * 512 + d];
        out_o[(size_t)b * 512 + d] = s * invZ;
    }

    const float* crow = cij + (size_t)b * TT;
    float* arow = out_a + (size_t)b * TT;
    for (int t = tid; t < TT; t += 256)
        arow[t] = __expf(crow[t] - M) * invZ;
}

// ---------------------------------------------------------------------------
// Launch  (attn_mma is the 4th launch -> ncu profiled slot)
// ---------------------------------------------------------------------------
extern "C" void kernel_launch(void* const* d_in, const int* in_sizes, int n_in,
                              void* d_out, int out_size)
{
    const float* hid  = (const float*)d_in[0];
    const float* E    = (const float*)d_in[1];
    const float* W    = (const float*)d_in[2];
    const float* U    = (const float*)d_in[3];
    const float* V    = (const float*)d_in[4];
    const float* bias = (const float*)d_in[5];
    const float* Wa   = (const float*)d_in[6];
    const float* ba   = (const float*)d_in[7];

    float* out_o = (float*)d_out;
    float* out_a = (float*)d_out + BB * DD;

    float *WWp, *cbp, *cp, *cijp, *poutp, *msp, *ssp;
    __half* BhT;
    cudaGetSymbolAddress((void**)&WWp,   g_WW);
    cudaGetSymbolAddress((void**)&cbp,   g_cb);
    cudaGetSymbolAddress((void**)&cp,    g_c);
    cudaGetSymbolAddress((void**)&BhT,   g_BhT);
    cudaGetSymbolAddress((void**)&cijp,  g_cij);
    cudaGetSymbolAddress((void**)&poutp, g_pout);
    cudaGetSymbolAddress((void**)&msp,   g_ms);
    cudaGetSymbolAddress((void**)&ssp,   g_ss);

    cudaFuncSetAttribute(attn_mma, cudaFuncAttributeMaxDynamicSharedMemorySize, SMEM_BYTES);

    // 1: [W;bias]@Wa -> WW, cb
    biggemm<<<dim3(9, 8), 256>>>(W, bias, Wa, ba, WWp, cbp, BhT, 0);
    // 2: U@Wa -> BhT (fp16, transposed)
    biggemm<<<dim3(8, 8), 256>>>(U, bias, Wa, ba, WWp, cbp, BhT, 1);
    // 3: c = hid@WW + cb
    cgemm<<<16, 256>>>(hid, WWp, cbp, cp);

    // 4 (profiled): fused GEMM + tanh·V + partial softmax/weighted-sum
    attn_mma<<<(BB * TT) / 128, 256, SMEM_BYTES>>>(E, BhT, cp, V, cijp,
                                                   poutp, msp, ssp);

    // 5: combine partials, write output + alphas
    finalize<<<BB, 256>>>(cijp, poutp, msp, ssp, out_o, out_a);
}

// round 15
// speedup vs baseline: 1.2461x; 1.2461x over previous
#include <cuda_runtime.h>
#include <cuda_fp16.h>
#include <cstdint>
#include <cstddef>

#define BB 32
#define TT 4096
#define DD 512
#define HH 512

// Scratch (device globals; no allocation allowed)
__device__ float g_WW[DD * HH];        // W@Wa (fp32)
__device__ float g_cb[HH];             // bias@Wa + ba
__device__ float g_c[BB * HH];         // hid@WW + cb
__device__ __half g_BhT[HH * DD];      // fp16 (U@Wa)^T  [h][k]
__device__ float g_cij[BB * TT];
__device__ float g_pout[1024 * DD];    // per-chunk partial weighted sums
__device__ float g_ms[1024];           // per-chunk local max
__device__ float g_ss[1024];           // per-chunk local sum-exp
// per-CTA fp16 A scratch: 1024 CTAs x 16 chunks x 10240B (smem tile layout)
__device__ __align__(16) unsigned char g_Escr[(size_t)1024 * 16 * 10240];

// ---------------------------------------------------------------------------
// PTX helpers (family-portable: mma.sync + cp.async + ldmatrix)
// ---------------------------------------------------------------------------
__device__ __forceinline__ uint32_t smem_u32(const void* p) {
    uint32_t a;
    asm("{ .reg .u64 t; cvta.to.shared.u64 t, %1; cvt.u32.u64 %0, t; }" : "=r"(a) : "l"(p));
    return a;
}
__device__ __forceinline__ void cpa16(uint32_t dst, const void* src) {
    asm volatile("cp.async.cg.shared.global [%0], [%1], 16;" :: "r"(dst), "l"(src));
}
#define CPA_COMMIT() asm volatile("cp.async.commit_group;" ::: "memory")
#define CPA_WAIT0()  asm volatile("cp.async.wait_group 0;" ::: "memory")

__device__ __forceinline__ float tanh_fast(float x) {
    float y;
    asm("tanh.approx.f32 %0, %1;" : "=f"(y) : "f"(x));
    return y;
}

__device__ __forceinline__ void ldm_x4(uint32_t* r, uint32_t addr) {
    asm volatile("ldmatrix.sync.aligned.m8n8.x4.shared.b16 {%0,%1,%2,%3}, [%4];"
                 : "=r"(r[0]), "=r"(r[1]), "=r"(r[2]), "=r"(r[3]) : "r"(addr));
}

__device__ __forceinline__ void mma16816h_full(float* d, const uint32_t* a, const uint32_t* b) {
    asm volatile(
        "mma.sync.aligned.m16n8k16.row.col.f32.f16.f16.f32 "
        "{%0,%1,%2,%3}, {%4,%5,%6,%7}, {%8,%9}, {%0,%1,%2,%3};"
        : "+f"(d[0]), "+f"(d[1]), "+f"(d[2]), "+f"(d[3])
        : "r"(a[0]), "r"(a[1]), "r"(a[2]), "r"(a[3]), "r"(b[0]), "r"(b[1]));
}
#define MMA16816H mma16816h_full

// ---------------------------------------------------------------------------
// biggemm: Y = X @ Wa, tiled 64x64x16, 256 threads, 4x4 micro-tile.
//   mode 0: X = [W; bias] (513 rows) -> WW fp32 rows<512, cb = row512 + ba
//   mode 1: X = U (512 rows)         -> BhT[col][row] = fp16(Y[row][col])
// ---------------------------------------------------------------------------
__global__ void __launch_bounds__(256)
biggemm(const float* __restrict__ X, const float* __restrict__ bias,
        const float* __restrict__ Wa, const float* __restrict__ ba,
        float* __restrict__ WW, float* __restrict__ cb,
        __half* __restrict__ BhT, int mode)
{
    __shared__ float As[16][68];
    __shared__ float Bs[16][64];
    const int tid = threadIdx.x;
    const int r0 = blockIdx.x * 64, c0 = blockIdx.y * 64;
    const int tx = tid & 15, ty = tid >> 4;

    float acc[4][4];
#pragma unroll
    for (int i = 0; i < 4; i++)
#pragma unroll
        for (int j = 0; j < 4; j++) acc[i][j] = 0.0f;

    for (int k0 = 0; k0 < 512; k0 += 16) {
        {
            int row = tid >> 2, seg = tid & 3;
            int gr = r0 + row;
            float4 v = make_float4(0.f, 0.f, 0.f, 0.f);
            if (gr < 512)                    v = *(const float4*)(X + (size_t)gr * 512 + k0 + seg * 4);
            else if (gr == 512 && mode == 0) v = *(const float4*)(bias + k0 + seg * 4);
            As[seg * 4 + 0][row] = v.x;
            As[seg * 4 + 1][row] = v.y;
            As[seg * 4 + 2][row] = v.z;
            As[seg * 4 + 3][row] = v.w;
        }
        {
            int kk = tid >> 4, seg = tid & 15;
            *(float4*)&Bs[kk][seg * 4] =
                *(const float4*)(Wa + (size_t)(k0 + kk) * 512 + c0 + seg * 4);
        }
        __syncthreads();

#pragma unroll
        for (int kk = 0; kk < 16; kk++) {
            float4 a4 = *(float4*)&As[kk][ty * 4];
            float4 b4 = *(float4*)&Bs[kk][tx * 4];
            float av[4] = {a4.x, a4.y, a4.z, a4.w};
            float bv[4] = {b4.x, b4.y, b4.z, b4.w};
#pragma unroll
            for (int i = 0; i < 4; i++)
#pragma unroll
                for (int j = 0; j < 4; j++) acc[i][j] += av[i] * bv[j];
        }
        __syncthreads();
    }

    if (mode == 0) {
#pragma unroll
        for (int i = 0; i < 4; i++) {
            int r = r0 + ty * 4 + i;
            if (r < 512) {
#pragma unroll
                for (int j = 0; j < 4; j++)
                    WW[(size_t)r * 512 + c0 + tx * 4 + j] = acc[i][j];
            } else if (r == 512) {
#pragma unroll
                for (int j = 0; j < 4; j++)
                    cb[c0 + tx * 4 + j] = acc[i][j] + ba[c0 + tx * 4 + j];
            }
        }
    } else {
#pragma unroll
        for (int j = 0; j < 4; j++) {
            int col = c0 + tx * 4 + j;
            __half2 p0 = __floats2half2_rn(acc[0][j], acc[1][j]);
            __half2 p1 = __floats2half2_rn(acc[2][j], acc[3][j]);
            *(uint2*)(BhT + (size_t)col * 512 + r0 + ty * 4) =
                make_uint2(*(uint32_t*)&p0, *(uint32_t*)&p1);
        }
    }
}

// ---------------------------------------------------------------------------
// cgemm: c[b][j] = sum_d hid[b][d] * WW[d][j] + cb[j]   (32 x 512, K=512)
// ---------------------------------------------------------------------------
__global__ void __launch_bounds__(256)
cgemm(const float* __restrict__ hid, const float* __restrict__ WW,
      const float* __restrict__ cb, float* __restrict__ c)
{
    __shared__ float hs[32][132];
    const int tid = threadIdx.x;
    const int col = blockIdx.x * 32 + (tid & 31);
    const int rg = tid >> 5;

    float acc[4] = {0.f, 0.f, 0.f, 0.f};
    for (int d0 = 0; d0 < 512; d0 += 128) {
        for (int v = tid; v < 1024; v += 256) {
            int row = v >> 5, seg = v & 31;
            *(float4*)&hs[row][seg * 4] =
                *(const float4*)(hid + (size_t)row * 512 + d0 + seg * 4);
        }
        __syncthreads();
#pragma unroll 8
        for (int dd = 0; dd < 128; dd++) {
            float bv = WW[(size_t)(d0 + dd) * 512 + col];
#pragma unroll
            for (int i = 0; i < 4; i++) acc[i] += hs[rg * 4 + i][dd] * bv;
        }
        __syncthreads();
    }
#pragma unroll
    for (int i = 0; i < 4; i++)
        c[(size_t)(rg * 4 + i) * 512 + col] = acc[i] + cb[col];
}

// ---------------------------------------------------------------------------
// Main mma.sync kernel + fused flash-style partial softmax/weighted-sum.
// h-pass 0: A = LDG fp32 -> cvt -> STS (smem) + STG (global fp16 scratch).
// h-passes 1-3: A = cp.async from scratch (L2-hot), no convert, no STS.
// B always cp.async fp16. Double-buffered, one syncthreads per chunk.
// ---------------------------------------------------------------------------
#define TILE_B  10240            /* 128 rows x 80B */
#define OFF_A   0                /* + buf*TILE_B, end 20480 */
#define OFF_B   20480            /* + buf*TILE_B, end 40960 */
#define OFF_CS  40960
#define OFF_VS  43008
#define OFF_EP  45056            /* 256 floats */
#define OFF_CIJ 46080            /* 128 floats */
#define OFF_RED 46592            /* 16 floats */
#define SMEM_BYTES 46720

#define SCR_CHUNK 10240
#define SCR_CTA   (16 * SCR_CHUNK)

__device__ __forceinline__ void ldg_E(float4* f, const float* Eb, int k0, int tid)
{
#pragma unroll
    for (int j = 0; j < 4; j++) {
        int u = tid + j * 256;
        int row = u >> 3, seg = u & 7;
        f[j] = *(const float4*)(Eb + (size_t)row * 512 + k0 + seg * 4);
    }
}

// convert + STS (smem) + STG (scratch, same tile layout)
__device__ __forceinline__ void sts_A_scr(uint32_t sb, int buf, const float4* f, int tid,
                                          unsigned char* scr_chunk)
{
#pragma unroll
    for (int j = 0; j < 4; j++) {
        int u = tid + j * 256;
        int row = u >> 3, seg = u & 7;
        __half2 h01 = __float22half2_rn(make_float2(f[j].x, f[j].y));
        __half2 h23 = __float22half2_rn(make_float2(f[j].z, f[j].w));
        uint32_t off = (uint32_t)(row * 80 + seg * 8);
        uint2 v = make_uint2(*(uint32_t*)&h01, *(uint32_t*)&h23);
        asm volatile("st.shared.v2.b32 [%0], {%1, %2};"
                     :: "r"(sb + OFF_A + (uint32_t)(buf * TILE_B) + off), "r"(v.x), "r"(v.y));
        *(uint2*)(scr_chunk + off) = v;
    }
}

__device__ __forceinline__ void load_A_scr(uint32_t sb, int buf,
                                           const unsigned char* scr, int kc, int tid)
{
    const unsigned char* src = scr + kc * SCR_CHUNK;
#pragma unroll
    for (int j = 0; j < 3; j++) {
        int u = tid + j * 256;               // 0..767, need 0..639
        if (u < 640)
            cpa16(sb + OFF_A + (uint32_t)(buf * TILE_B + u * 16), src + u * 16);
    }
}

__device__ __forceinline__ void load_B_chunk(
    uint32_t sb, int buf, const __half* Bt, int h0, int k0, int tid)
{
#pragma unroll
    for (int j = 0; j < 2; j++) {
        int u = tid + j * 256;
        int row = u >> 2, seg = u & 3;
        const __half* src = Bt + (size_t)(h0 + row) * 512 + k0 + seg * 8;
        uint32_t dst = sb + OFF_B + (uint32_t)(buf * TILE_B + row * 80 + seg * 16);
        cpa16(dst, src);
    }
}

__global__ void __launch_bounds__(256, 2)
attn_mma(const float* __restrict__ E, const __half* __restrict__ Bt,
         const float* __restrict__ c, const float* __restrict__ V,
         float* __restrict__ cij,
         float* __restrict__ pout, float* __restrict__ ms, float* __restrict__ ss,
         unsigned char* __restrict__ Escr)
{
    extern __shared__ char sm[];
    const uint32_t sb = smem_u32(sm);
    const int tid = threadIdx.x, wid = tid >> 5, lane = tid & 31;
    const int warp_m = wid & 3;
    const int warp_n = wid >> 2;
    const int lq = lane >> 2, lr = lane & 3;
    const int row0 = blockIdx.x * 128;
    const int b = row0 >> 12;

    const float* Eb = E + (size_t)row0 * 512;
    unsigned char* scr = Escr + (size_t)blockIdx.x * SCR_CTA;

    float* c_s   = (float*)(sm + OFF_CS);
    float* V_s   = (float*)(sm + OFF_VS);
    float* ep_s  = (float*)(sm + OFF_EP);
    float* cij_s = (float*)(sm + OFF_CIJ);
    float* red_s = (float*)(sm + OFF_RED);

    for (int i = tid; i < 512; i += 256) {
        c_s[i] = c[(size_t)b * 512 + i];
        V_s[i] = V[i];
    }
    if (tid < 128) cij_s[tid] = 0.0f;
    __syncthreads();

    const int amat = lane >> 3, arr = lane & 7;
    const int bpr  = lane >> 3;

    for (int hp = 0; hp < 4; hp++) {
        const int h0 = hp * 128;
        float acc[2][8][4];
#pragma unroll
        for (int fm = 0; fm < 2; fm++)
#pragma unroll
            for (int fn = 0; fn < 8; fn++)
#pragma unroll
                for (int j = 0; j < 4; j++) acc[fm][fn][j] = 0.0f;

        float4 ereg[4];
        if (hp == 0) {
            ldg_E(ereg, Eb, 0, tid);
        } else {
            load_A_scr(sb, 0, scr, 0, tid);
        }
        load_B_chunk(sb, 0, Bt, h0, 0, tid);
        CPA_COMMIT();

        for (int kc = 0; kc < 16; kc++) {
            const int buf = kc & 1;
            CPA_WAIT0();
            if (hp == 0) sts_A_scr(sb, buf, ereg, tid, scr + kc * SCR_CHUNK);
            __syncthreads();                 // tiles visible; prior MMA done

            if (kc < 15) {
                if (hp == 0) {
                    load_B_chunk(sb, buf ^ 1, Bt, h0, (kc + 1) * 32, tid);
                    CPA_COMMIT();
                    ldg_E(ereg, Eb, (kc + 1) * 32, tid);   // overlaps MMA
                } else {
                    load_A_scr(sb, buf ^ 1, scr, kc + 1, tid);
                    load_B_chunk(sb, buf ^ 1, Bt, h0, (kc + 1) * 32, tid);
                    CPA_COMMIT();
                }
            }

            const uint32_t abase = sb + OFF_A + (uint32_t)(buf * TILE_B);
            const uint32_t bbase = sb + OFF_B + (uint32_t)(buf * TILE_B);

#pragma unroll
            for (int ks = 0; ks < 2; ks++) {
                uint32_t aF[2][4];
#pragma unroll
                for (int fm = 0; fm < 2; fm++) {
                    int arow = warp_m * 32 + fm * 16 + (amat & 1) * 8 + arr;
                    ldm_x4(aF[fm], abase + (uint32_t)(arow * 80 + ks * 32 + (amat >> 1) * 16));
                }
#pragma unroll
                for (int fnp = 0; fnp < 4; fnp++) {
                    int nrow = warp_n * 64 + fnp * 16 + (bpr >> 1) * 8 + arr;
                    uint32_t bF[4];
                    ldm_x4(bF, bbase + (uint32_t)(nrow * 80 + ks * 32 + (bpr & 1) * 16));
#pragma unroll
                    for (int fm = 0; fm < 2; fm++) {
                        MMA16816H(acc[fm][fnp * 2],     aF[fm], bF);
                        MMA16816H(acc[fm][fnp * 2 + 1], aF[fm], bF + 2);
                    }
                }
            }
        }

        // ---- epilogue for this h-pass (MUFU.TANH) ----
        float rsum[4] = {0.f, 0.f, 0.f, 0.f};
#pragma unroll
        for (int fm = 0; fm < 2; fm++)
#pragma unroll
            for (int fn = 0; fn < 8; fn++) {
                int h = h0 + warp_n * 64 + fn * 8 + lr * 2;
                float v0 = tanh_fast(acc[fm][fn][0] + c_s[h])     * V_s[h];
                float v1 = tanh_fast(acc[fm][fn][1] + c_s[h + 1]) * V_s[h + 1];
                float v2 = tanh_fast(acc[fm][fn][2] + c_s[h])     * V_s[h];
                float v3 = tanh_fast(acc[fm][fn][3] + c_s[h + 1]) * V_s[h + 1];
                rsum[fm * 2]     += v0 + v1;
                rsum[fm * 2 + 1] += v2 + v3;
            }
#pragma unroll
        for (int j = 0; j < 4; j++) {
            rsum[j] += __shfl_xor_sync(0xffffffffu, rsum[j], 1);
            rsum[j] += __shfl_xor_sync(0xffffffffu, rsum[j], 2);
        }
        if (lr == 0) {
#pragma unroll
            for (int fm = 0; fm < 2; fm++) {
                int r = warp_m * 32 + fm * 16 + lq;
                ep_s[warp_n * 128 + r]     = rsum[fm * 2];
                ep_s[warp_n * 128 + r + 8] = rsum[fm * 2 + 1];
            }
        }
        __syncthreads();
        if (tid < 128) cij_s[tid] += ep_s[tid] + ep_s[128 + tid];
        __syncthreads();
    }

    if (tid < 128) cij[row0 + tid] = cij_s[tid];
    __syncthreads();

    // ---- fused flash-style partial softmax + weighted sum ----
    float v = (tid < 128) ? cij_s[tid] : -1e30f;
#pragma unroll
    for (int off = 16; off; off >>= 1) v = fmaxf(v, __shfl_xor_sync(0xffffffffu, v, off));
    if (lane == 0) red_s[wid] = v;
    __syncthreads();
    const float mhat = fmaxf(fmaxf(red_s[0], red_s[1]), fmaxf(red_s[2], red_s[3]));

    float p = 0.0f;
    if (tid < 128) { p = __expf(cij_s[tid] - mhat); ep_s[tid] = p; }
    float sv = p;
#pragma unroll
    for (int off = 16; off; off >>= 1) sv += __shfl_xor_sync(0xffffffffu, sv, off);
    if (lane == 0) red_s[8 + wid] = sv;
    __syncthreads();
    const float S = red_s[8] + red_s[9] + red_s[10] + red_s[11];
    if (tid == 0) { ms[blockIdx.x] = mhat; ss[blockIdx.x] = S; }

    float a0 = 0.0f, a1 = 0.0f;
    for (int i = 0; i < 128; i += 8) {
#pragma unroll
        for (int j = 0; j < 8; j++) {
            float pij = ep_s[i + j];
            a0 = fmaf(pij, Eb[(size_t)(i + j) * 512 + tid],       a0);
            a1 = fmaf(pij, Eb[(size_t)(i + j) * 512 + tid + 256], a1);
        }
    }
    pout[(size_t)blockIdx.x * 512 + tid]       = a0;
    pout[(size_t)blockIdx.x * 512 + tid + 256] = a1;
}

// ---------------------------------------------------------------------------
// Finalize: combine 32 chunk-partials per batch (flash rescale) + write alphas.
// ---------------------------------------------------------------------------
__global__ void __launch_bounds__(256)
finalize(const float* __restrict__ cij, const float* __restrict__ pout,
         const float* __restrict__ ms, const float* __restrict__ ss,
         float* __restrict__ out_o, float* __restrict__ out_a)
{
    __shared__ float w_s[32];
    __shared__ float MZ[2];
    const int b = blockIdx.x, tid = threadIdx.x;

    if (tid < 32) {
        float m = ms[b * 32 + tid];
        float M = m;
#pragma unroll
        for (int off = 16; off; off >>= 1) M = fmaxf(M, __shfl_xor_sync(0xffffffffu, M, off));
        float w = __expf(m - M);
        w_s[tid] = w;
        float z = w * ss[b * 32 + tid];
#pragma unroll
        for (int off = 16; off; off >>= 1) z += __shfl_xor_sync(0xffffffffu, z, off);
        if (tid == 0) { MZ[0] = M; MZ[1] = z; }
    }
    __syncthreads();
    const float M = MZ[0], invZ = 1.0f / MZ[1];

    for (int d = tid; d < 512; d += 256) {
        float s = 0.0f;
#pragma unroll
        for (int i = 0; i < 32; i++)
            s += w_s[i] * pout[(size_t)(b * 32 + i) * 512 + d];
        out_o[(size_t)b * 512 + d] = s * invZ;
    }

    const float* crow = cij + (size_t)b * TT;
    float* arow = out_a + (size_t)b * TT;
    for (int t = tid; t < TT; t += 256)
        arow[t] = __expf(crow[t] - M) * invZ;
}

// ---------------------------------------------------------------------------
// Launch  (attn_mma is the 4th launch -> ncu profiled slot)
// ---------------------------------------------------------------------------
extern "C" void kernel_launch(void* const* d_in, const int* in_sizes, int n_in,
                              void* d_out, int out_size)
{
    const float* hid  = (const float*)d_in[0];
    const float* E    = (const float*)d_in[1];
    const float* W    = (const float*)d_in[2];
    const float* U    = (const float*)d_in[3];
    const float* V    = (const float*)d_in[4];
    const float* bias = (const float*)d_in[5];
    const float* Wa   = (const float*)d_in[6];
    const float* ba   = (const float*)d_in[7];

    float* out_o = (float*)d_out;
    float* out_a = (float*)d_out + BB * DD;

    float *WWp, *cbp, *cp, *cijp, *poutp, *msp, *ssp;
    __half* BhT;
    unsigned char* scrp;
    cudaGetSymbolAddress((void**)&WWp,   g_WW);
    cudaGetSymbolAddress((void**)&cbp,   g_cb);
    cudaGetSymbolAddress((void**)&cp,    g_c);
    cudaGetSymbolAddress((void**)&BhT,   g_BhT);
    cudaGetSymbolAddress((void**)&cijp,  g_cij);
    cudaGetSymbolAddress((void**)&poutp, g_pout);
    cudaGetSymbolAddress((void**)&msp,   g_ms);
    cudaGetSymbolAddress((void**)&ssp,   g_ss);
    cudaGetSymbolAddress((void**)&scrp,  g_Escr);

    cudaFuncSetAttribute(attn_mma, cudaFuncAttributeMaxDynamicSharedMemorySize, SMEM_BYTES);

    // 1: [W;bias]@Wa -> WW, cb
    biggemm<<<dim3(9, 8), 256>>>(W, bias, Wa, ba, WWp, cbp, BhT, 0);
    // 2: U@Wa -> BhT (fp16, transposed)
    biggemm<<<dim3(8, 8), 256>>>(U, bias, Wa, ba, WWp, cbp, BhT, 1);
    // 3: c = hid@WW + cb
    cgemm<<<16, 256>>>(hid, WWp, cbp, cp);

    // 4 (profiled): fused GEMM + tanh·V + partial softmax/weighted-sum
    attn_mma<<<(BB * TT) / 128, 256, SMEM_BYTES>>>(E, BhT, cp, V, cijp,
                                                   poutp, msp, ssp, scrp);

    // 5: combine partials, write output + alphas
    finalize<<<BB, 256>>>(cijp, poutp, msp, ssp, out_o, out_a);
}

// round 16
// speedup vs baseline: 1.5076x; 1.2098x over previous
#include <cuda_runtime.h>
#include <cuda_fp16.h>
#include <cstdint>
#include <cstddef>

#define BB 32
#define TT 4096
#define DD 512
#define HH 512

// Scratch (device globals; no allocation allowed)
__device__ float g_hp[BB * HH];        // hid@W + bias
__device__ float g_c[BB * HH];         // (hid@W+bias)@Wa + ba
__device__ __half g_BhT[HH * DD];      // fp16 (U@Wa)^T  [h][k]
__device__ float g_cij[BB * TT];
__device__ float g_pout[1024 * DD];    // per-chunk partial weighted sums
__device__ float g_ms[1024];           // per-chunk local max
__device__ float g_ss[1024];           // per-chunk local sum-exp

// ---------------------------------------------------------------------------
// PTX helpers (family-portable: mma.sync + cp.async + ldmatrix)
// ---------------------------------------------------------------------------
__device__ __forceinline__ uint32_t smem_u32(const void* p) {
    uint32_t a;
    asm("{ .reg .u64 t; cvta.to.shared.u64 t, %1; cvt.u32.u64 %0, t; }" : "=r"(a) : "l"(p));
    return a;
}
__device__ __forceinline__ void cpa16(uint32_t dst, const void* src) {
    asm volatile("cp.async.cg.shared.global [%0], [%1], 16;" :: "r"(dst), "l"(src));
}
#define CPA_COMMIT() asm volatile("cp.async.commit_group;" ::: "memory")
#define CPA_WAIT0()  asm volatile("cp.async.wait_group 0;" ::: "memory")

__device__ __forceinline__ float tanh_fast(float x) {
    float y;
    asm("tanh.approx.f32 %0, %1;" : "=f"(y) : "f"(x));
    return y;
}

__device__ __forceinline__ void ldm_x4(uint32_t* r, uint32_t addr) {
    asm volatile("ldmatrix.sync.aligned.m8n8.x4.shared.b16 {%0,%1,%2,%3}, [%4];"
                 : "=r"(r[0]), "=r"(r[1]), "=r"(r[2]), "=r"(r[3]) : "r"(addr));
}

__device__ __forceinline__ void mma16816h_full(float* d, const uint32_t* a, const uint32_t* b) {
    asm volatile(
        "mma.sync.aligned.m16n8k16.row.col.f32.f16.f16.f32 "
        "{%0,%1,%2,%3}, {%4,%5,%6,%7}, {%8,%9}, {%0,%1,%2,%3};"
        : "+f"(d[0]), "+f"(d[1]), "+f"(d[2]), "+f"(d[3])
        : "r"(a[0]), "r"(a[1]), "r"(a[2]), "r"(a[3]), "r"(b[0]), "r"(b[1]));
}
#define MMA16816H mma16816h_full

// ---------------------------------------------------------------------------
// smallgemm: out[32,512] = A[32,512] @ B[512,512] + addvec
// 64 blocks x 256 threads; block covers 8 cols; thread -> 1 output.
// A and B tiles staged in smem; k-tile 64.
// ---------------------------------------------------------------------------
__global__ void __launch_bounds__(256)
smallgemm(const float* __restrict__ A, const float* __restrict__ B,
          const float* __restrict__ addvec, float* __restrict__ out)
{
    __shared__ float As[32][64];
    __shared__ float Bs[64][8];
    const int tid = threadIdx.x;
    const int row = tid >> 3;            // 0..31
    const int cl  = tid & 7;             // 0..7
    const int col = blockIdx.x * 8 + cl;

    float acc = 0.0f;
    for (int k0 = 0; k0 < 512; k0 += 64) {
        // A tile: 32x64 = 2048 floats, 8 per thread (2 float4)
#pragma unroll
        for (int j = 0; j < 2; j++) {
            int u = tid + j * 256;       // 0..511 float4 units
            int r = u >> 4, s = u & 15;
            *(float4*)&As[r][s * 4] = *(const float4*)(A + (size_t)r * 512 + k0 + s * 4);
        }
        // B tile: 64x8 = 512 floats, 2 per thread
#pragma unroll
        for (int j = 0; j < 2; j++) {
            int u = tid + j * 256;       // 0..511
            int kk = u >> 3, cc = u & 7;
            Bs[kk][cc] = B[(size_t)(k0 + kk) * 512 + blockIdx.x * 8 + cc];
        }
        __syncthreads();
#pragma unroll 16
        for (int kk = 0; kk < 64; kk++)
            acc += As[row][kk] * Bs[kk][cl];
        __syncthreads();
    }
    out[(size_t)row * 512 + col] = acc + (addvec ? addvec[col] : 0.0f);
}

// ---------------------------------------------------------------------------
// biggemm (mode 1 only): BhT[col][row] = fp16((U @ Wa)[row][col])
// tiled 64x64x16, 256 threads, 4x4 micro-tile.
// ---------------------------------------------------------------------------
__global__ void __launch_bounds__(256)
biggemmT(const float* __restrict__ X, const float* __restrict__ Wa,
         __half* __restrict__ BhT)
{
    __shared__ float As[16][68];
    __shared__ float Bs[16][64];
    const int tid = threadIdx.x;
    const int r0 = blockIdx.x * 64, c0 = blockIdx.y * 64;
    const int tx = tid & 15, ty = tid >> 4;

    float acc[4][4];
#pragma unroll
    for (int i = 0; i < 4; i++)
#pragma unroll
        for (int j = 0; j < 4; j++) acc[i][j] = 0.0f;

    for (int k0 = 0; k0 < 512; k0 += 16) {
        {
            int row = tid >> 2, seg = tid & 3;
            float4 v = *(const float4*)(X + (size_t)(r0 + row) * 512 + k0 + seg * 4);
            As[seg * 4 + 0][row] = v.x;
            As[seg * 4 + 1][row] = v.y;
            As[seg * 4 + 2][row] = v.z;
            As[seg * 4 + 3][row] = v.w;
        }
        {
            int kk = tid >> 4, seg = tid & 15;
            *(float4*)&Bs[kk][seg * 4] =
                *(const float4*)(Wa + (size_t)(k0 + kk) * 512 + c0 + seg * 4);
        }
        __syncthreads();

#pragma unroll
        for (int kk = 0; kk < 16; kk++) {
            float4 a4 = *(float4*)&As[kk][ty * 4];
            float4 b4 = *(float4*)&Bs[kk][tx * 4];
            float av[4] = {a4.x, a4.y, a4.z, a4.w};
            float bv[4] = {b4.x, b4.y, b4.z, b4.w};
#pragma unroll
            for (int i = 0; i < 4; i++)
#pragma unroll
                for (int j = 0; j < 4; j++) acc[i][j] += av[i] * bv[j];
        }
        __syncthreads();
    }

#pragma unroll
    for (int j = 0; j < 4; j++) {
        int col = c0 + tx * 4 + j;
        __half2 p0 = __floats2half2_rn(acc[0][j], acc[1][j]);
        __half2 p1 = __floats2half2_rn(acc[2][j], acc[3][j]);
        *(uint2*)(BhT + (size_t)col * 512 + r0 + ty * 4) =
            make_uint2(*(uint32_t*)&p0, *(uint32_t*)&p1);
    }
}

// ---------------------------------------------------------------------------
// Main mma.sync kernel + fused flash-style partial softmax/weighted-sum.
// (EXACT R10 pipeline: LDG fp32 E -> regs -> cvt -> STS; B cp.async;
//  double-buffered, one syncthreads per chunk; ldmatrix + HMMA.)
// ---------------------------------------------------------------------------
#define TILE_B  10240            /* 128 rows x 80B */
#define OFF_A   0                /* + buf*TILE_B, end 20480 */
#define OFF_B   20480            /* + buf*TILE_B, end 40960 */
#define OFF_CS  40960
#define OFF_VS  43008
#define OFF_EP  45056            /* 256 floats */
#define OFF_CIJ 46080            /* 128 floats */
#define OFF_RED 46592            /* 16 floats */
#define SMEM_BYTES 46720

__device__ __forceinline__ void ldg_E(float4* f, const float* Eb, int k0, int tid)
{
#pragma unroll
    for (int j = 0; j < 4; j++) {
        int u = tid + j * 256;
        int row = u >> 3, seg = u & 7;
        f[j] = *(const float4*)(Eb + (size_t)row * 512 + k0 + seg * 4);
    }
}

__device__ __forceinline__ void sts_A(uint32_t sb, int buf, const float4* f, int tid)
{
#pragma unroll
    for (int j = 0; j < 4; j++) {
        int u = tid + j * 256;
        int row = u >> 3, seg = u & 7;
        __half2 h01 = __float22half2_rn(make_float2(f[j].x, f[j].y));
        __half2 h23 = __float22half2_rn(make_float2(f[j].z, f[j].w));
        uint32_t dst = sb + OFF_A + (uint32_t)(buf * TILE_B + row * 80 + seg * 8);
        uint2 v = make_uint2(*(uint32_t*)&h01, *(uint32_t*)&h23);
        asm volatile("st.shared.v2.b32 [%0], {%1, %2};" :: "r"(dst), "r"(v.x), "r"(v.y));
    }
}

__device__ __forceinline__ void load_B_chunk(
    uint32_t sb, int buf, const __half* Bt, int h0, int k0, int tid)
{
#pragma unroll
    for (int j = 0; j < 2; j++) {
        int u = tid + j * 256;
        int row = u >> 2, seg = u & 3;
        const __half* src = Bt + (size_t)(h0 + row) * 512 + k0 + seg * 8;
        uint32_t dst = sb + OFF_B + (uint32_t)(buf * TILE_B + row * 80 + seg * 16);
        cpa16(dst, src);
    }
}

__global__ void __launch_bounds__(256, 2)
attn_mma(const float* __restrict__ E, const __half* __restrict__ Bt,
         const float* __restrict__ c, const float* __restrict__ V,
         float* __restrict__ cij,
         float* __restrict__ pout, float* __restrict__ ms, float* __restrict__ ss)
{
    extern __shared__ char sm[];
    const uint32_t sb = smem_u32(sm);
    const int tid = threadIdx.x, wid = tid >> 5, lane = tid & 31;
    const int warp_m = wid & 3;
    const int warp_n = wid >> 2;
    const int lq = lane >> 2, lr = lane & 3;
    const int row0 = blockIdx.x * 128;
    const int b = row0 >> 12;

    const float* Eb = E + (size_t)row0 * 512;

    float* c_s   = (float*)(sm + OFF_CS);
    float* V_s   = (float*)(sm + OFF_VS);
    float* ep_s  = (float*)(sm + OFF_EP);
    float* cij_s = (float*)(sm + OFF_CIJ);
    float* red_s = (float*)(sm + OFF_RED);

    for (int i = tid; i < 512; i += 256) {
        c_s[i] = c[(size_t)b * 512 + i];
        V_s[i] = V[i];
    }
    if (tid < 128) cij_s[tid] = 0.0f;
    __syncthreads();

    const int amat = lane >> 3, arr = lane & 7;
    const int bpr  = lane >> 3;

    for (int hp = 0; hp < 4; hp++) {
        const int h0 = hp * 128;
        float acc[2][8][4];
#pragma unroll
        for (int fm = 0; fm < 2; fm++)
#pragma unroll
            for (int fn = 0; fn < 8; fn++)
#pragma unroll
                for (int j = 0; j < 4; j++) acc[fm][fn][j] = 0.0f;

        float4 ereg[4];
        ldg_E(ereg, Eb, 0, tid);
        load_B_chunk(sb, 0, Bt, h0, 0, tid);
        CPA_COMMIT();

        for (int kc = 0; kc < 16; kc++) {
            const int buf = kc & 1;
            CPA_WAIT0();
            sts_A(sb, buf, ereg, tid);
            __syncthreads();

            if (kc < 15) {
                load_B_chunk(sb, buf ^ 1, Bt, h0, (kc + 1) * 32, tid);
                CPA_COMMIT();
                ldg_E(ereg, Eb, (kc + 1) * 32, tid);
            }

            const uint32_t abase = sb + OFF_A + (uint32_t)(buf * TILE_B);
            const uint32_t bbase = sb + OFF_B + (uint32_t)(buf * TILE_B);

#pragma unroll
            for (int ks = 0; ks < 2; ks++) {
                uint32_t aF[2][4];
#pragma unroll
                for (int fm = 0; fm < 2; fm++) {
                    int arow = warp_m * 32 + fm * 16 + (amat & 1) * 8 + arr;
                    ldm_x4(aF[fm], abase + (uint32_t)(arow * 80 + ks * 32 + (amat >> 1) * 16));
                }
#pragma unroll
                for (int fnp = 0; fnp < 4; fnp++) {
                    int nrow = warp_n * 64 + fnp * 16 + (bpr >> 1) * 8 + arr;
                    uint32_t bF[4];
                    ldm_x4(bF, bbase + (uint32_t)(nrow * 80 + ks * 32 + (bpr & 1) * 16));
#pragma unroll
                    for (int fm = 0; fm < 2; fm++) {
                        MMA16816H(acc[fm][fnp * 2],     aF[fm], bF);
                        MMA16816H(acc[fm][fnp * 2 + 1], aF[fm], bF + 2);
                    }
                }
            }
        }

        // ---- epilogue for this h-pass (MUFU.TANH) ----
        float rsum[4] = {0.f, 0.f, 0.f, 0.f};
#pragma unroll
        for (int fm = 0; fm < 2; fm++)
#pragma unroll
            for (int fn = 0; fn < 8; fn++) {
                int h = h0 + warp_n * 64 + fn * 8 + lr * 2;
                float v0 = tanh_fast(acc[fm][fn][0] + c_s[h])     * V_s[h];
                float v1 = tanh_fast(acc[fm][fn][1] + c_s[h + 1]) * V_s[h + 1];
                float v2 = tanh_fast(acc[fm][fn][2] + c_s[h])     * V_s[h];
                float v3 = tanh_fast(acc[fm][fn][3] + c_s[h + 1]) * V_s[h + 1];
                rsum[fm * 2]     += v0 + v1;
                rsum[fm * 2 + 1] += v2 + v3;
            }
#pragma unroll
        for (int j = 0; j < 4; j++) {
            rsum[j] += __shfl_xor_sync(0xffffffffu, rsum[j], 1);
            rsum[j] += __shfl_xor_sync(0xffffffffu, rsum[j], 2);
        }
        if (lr == 0) {
#pragma unroll
            for (int fm = 0; fm < 2; fm++) {
                int r = warp_m * 32 + fm * 16 + lq;
                ep_s[warp_n * 128 + r]     = rsum[fm * 2];
                ep_s[warp_n * 128 + r + 8] = rsum[fm * 2 + 1];
            }
        }
        __syncthreads();
        if (tid < 128) cij_s[tid] += ep_s[tid] + ep_s[128 + tid];
        __syncthreads();
    }

    if (tid < 128) cij[row0 + tid] = cij_s[tid];
    __syncthreads();

    // ---- fused flash-style partial softmax + weighted sum ----
    float v = (tid < 128) ? cij_s[tid] : -1e30f;
#pragma unroll
    for (int off = 16; off; off >>= 1) v = fmaxf(v, __shfl_xor_sync(0xffffffffu, v, off));
    if (lane == 0) red_s[wid] = v;
    __syncthreads();
    const float mhat = fmaxf(fmaxf(red_s[0], red_s[1]), fmaxf(red_s[2], red_s[3]));

    float p = 0.0f;
    if (tid < 128) { p = __expf(cij_s[tid] - mhat); ep_s[tid] = p; }
    float sv = p;
#pragma unroll
    for (int off = 16; off; off >>= 1) sv += __shfl_xor_sync(0xffffffffu, sv, off);
    if (lane == 0) red_s[8 + wid] = sv;
    __syncthreads();
    const float S = red_s[8] + red_s[9] + red_s[10] + red_s[11];
    if (tid == 0) { ms[blockIdx.x] = mhat; ss[blockIdx.x] = S; }

    float a0 = 0.0f, a1 = 0.0f;
    for (int i = 0; i < 128; i += 8) {
#pragma unroll
        for (int j = 0; j < 8; j++) {
            float pij = ep_s[i + j];
            a0 = fmaf(pij, Eb[(size_t)(i + j) * 512 + tid],       a0);
            a1 = fmaf(pij, Eb[(size_t)(i + j) * 512 + tid + 256], a1);
        }
    }
    pout[(size_t)blockIdx.x * 512 + tid]       = a0;
    pout[(size_t)blockIdx.x * 512 + tid + 256] = a1;
}

// ---------------------------------------------------------------------------
// Finalize: combine 32 chunk-partials per batch (flash rescale) + write alphas.
// ---------------------------------------------------------------------------
__global__ void __launch_bounds__(256)
finalize(const float* __restrict__ cij, const float* __restrict__ pout,
         const float* __restrict__ ms, const float* __restrict__ ss,
         float* __restrict__ out_o, float* __restrict__ out_a)
{
    __shared__ float w_s[32];
    __shared__ float MZ[2];
    const int b = blockIdx.x, tid = threadIdx.x;

    if (tid < 32) {
        float m = ms[b * 32 + tid];
        float M = m;
#pragma unroll
        for (int off = 16; off; off >>= 1) M = fmaxf(M, __shfl_xor_sync(0xffffffffu, M, off));
        float w = __expf(m - M);
        w_s[tid] = w;
        float z = w * ss[b * 32 + tid];
#pragma unroll
        for (int off = 16; off; off >>= 1) z += __shfl_xor_sync(0xffffffffu, z, off);
        if (tid == 0) { MZ[0] = M; MZ[1] = z; }
    }
    __syncthreads();
    const float M = MZ[0], invZ = 1.0f / MZ[1];

    for (int d = tid; d < 512; d += 256) {
        float s = 0.0f;
#pragma unroll
        for (int i = 0; i < 32; i++)
            s += w_s[i] * pout[(size_t)(b * 32 + i) * 512 + d];
        out_o[(size_t)b * 512 + d] = s * invZ;
    }

    const float* crow = cij + (size_t)b * TT;
    float* arow = out_a + (size_t)b * TT;
    for (int t = tid; t < TT; t += 256)
        arow[t] = __expf(crow[t] - M) * invZ;
}

// ---------------------------------------------------------------------------
// Launch  (attn_mma is the 4th launch -> ncu profiled slot)
// ---------------------------------------------------------------------------
extern "C" void kernel_launch(void* const* d_in, const int* in_sizes, int n_in,
                              void* d_out, int out_size)
{
    const float* hid  = (const float*)d_in[0];
    const float* E    = (const float*)d_in[1];
    const float* W    = (const float*)d_in[2];
    const float* U    = (const float*)d_in[3];
    const float* V    = (const float*)d_in[4];
    const float* bias = (const float*)d_in[5];
    const float* Wa   = (const float*)d_in[6];
    const float* ba   = (const float*)d_in[7];

    float* out_o = (float*)d_out;
    float* out_a = (float*)d_out + BB * DD;

    float *hpP, *cp, *cijp, *poutp, *msp, *ssp;
    __half* BhT;
    cudaGetSymbolAddress((void**)&hpP,   g_hp);
    cudaGetSymbolAddress((void**)&cp,    g_c);
    cudaGetSymbolAddress((void**)&BhT,   g_BhT);
    cudaGetSymbolAddress((void**)&cijp,  g_cij);
    cudaGetSymbolAddress((void**)&poutp, g_pout);
    cudaGetSymbolAddress((void**)&msp,   g_ms);
    cudaGetSymbolAddress((void**)&ssp,   g_ss);

    cudaFuncSetAttribute(attn_mma, cudaFuncAttributeMaxDynamicSharedMemorySize, SMEM_BYTES);

    // 1: hp = hid@W + bias        (64 blocks, ~5us)
    smallgemm<<<64, 256>>>(hid, W, bias, hpP);
    // 2: BhT = fp16((U@Wa)^T)     (64 blocks, ~20us)
    biggemmT<<<dim3(8, 8), 256>>>(U, Wa, BhT);
    // 3: c = hp@Wa + ba           (64 blocks, ~5us)
    smallgemm<<<64, 256>>>(hpP, Wa, ba, cp);

    // 4 (profiled): fused GEMM + tanh·V + partial softmax/weighted-sum
    attn_mma<<<(BB * TT) / 128, 256, SMEM_BYTES>>>(E, BhT, cp, V, cijp,
                                                   poutp, msp, ssp);

    // 5: combine partials, write output + alphas
    finalize<<<BB, 256>>>(cijp, poutp, msp, ssp, out_o, out_a);
}